// round 1
// baseline (speedup 1.0000x reference)
#include <cuda_runtime.h>
#include <math.h>
#include <stdint.h>

#define NN 50000
#define EE 800000
#define INC 32
#define HIDC 64

// ---------------- scratch (device globals; no runtime allocation) ----------
__device__ float g_e[EE * 16];       // edge MLP output
__device__ float g_EX[EE * 16];      // exp(score) per edge: [pass(2)][gate(4)][head(2)]
__device__ float g_DEN[NN * 16];     // softmax denominators per dst node
__device__ float g_XLx[(size_t)NN * 256];  // x @ Wlx + blx, per gate
__device__ float g_XRx[(size_t)NN * 256];
__device__ float g_XLh[(size_t)NN * 256];
__device__ float g_XRh[(size_t)NN * 256];
__device__ float g_GATES[(size_t)NN * 256]; // accumulated ax+ah per gate

// ---------------- zero init -------------------------------------------------
__global__ void k_zero() {
    size_t i = (size_t)blockIdx.x * blockDim.x + threadIdx.x;
    const float4 z = make_float4(0.f, 0.f, 0.f, 0.f);
    size_t nd = (size_t)NN * 16 / 4;    // 200000
    size_t ng = (size_t)NN * 256 / 4;   // 3.2M
    if (i < nd) ((float4*)g_DEN)[i] = z;
    if (i < ng) ((float4*)g_GATES)[i] = z;
}

// ---------------- edge MLP: e = gelu(ea@Wm1+bm1)@Wm2+bm2 -------------------
__global__ void k_edge_mlp(const float* __restrict__ ea,
                           const float* __restrict__ Wm1, const float* __restrict__ bm1,
                           const float* __restrict__ Wm2, const float* __restrict__ bm2) {
    __shared__ float sW1[256], sW2[256], sb1[16], sb2[16];
    int t = threadIdx.x;
    sW1[t] = Wm1[t];
    sW2[t] = Wm2[t];
    if (t < 16) { sb1[t] = bm1[t]; sb2[t] = bm2[t]; }
    __syncthreads();
    int e = blockIdx.x * 256 + t;  // EE divisible by 256

    float4 va[4];
    const float4* p = (const float4*)(ea + (size_t)e * 16);
    va[0] = p[0]; va[1] = p[1]; va[2] = p[2]; va[3] = p[3];
    const float* a = (const float*)va;

    float h[16];
#pragma unroll
    for (int j = 0; j < 16; j++) {
        float s = sb1[j];
#pragma unroll
        for (int k = 0; k < 16; k++) s = fmaf(a[k], sW1[k * 16 + j], s);
        h[j] = 0.5f * s * (1.0f + erff(s * 0.70710678118654752f));
    }
    float4 vo[4];
    float* o = (float*)vo;
#pragma unroll
    for (int j = 0; j < 16; j++) {
        float s = sb2[j];
#pragma unroll
        for (int k = 0; k < 16; k++) s = fmaf(h[k], sW2[k * 16 + j], s);
        o[j] = s;
    }
    float4* q = (float4*)(g_e + (size_t)e * 16);
    q[0] = vo[0]; q[1] = vo[1]; q[2] = vo[2]; q[3] = vo[3];
}

// ---------------- node projections: OUT[n][g*64+o] = X[n]@W[g] + B[g] ------
template <int IN>
__global__ void k_proj(const float* __restrict__ X, const float* __restrict__ W,
                       const float* __restrict__ B, float* __restrict__ OUT) {
    __shared__ __align__(16) float xs[64 * (IN + 1)];
    __shared__ __align__(16) float ws[IN * 64];
    int t = threadIdx.x;
    int n0 = blockIdx.x * 64;
    for (int idx = t; idx < 64 * IN; idx += 256) {
        int nl = idx / IN, i = idx % IN;
        int n = n0 + nl;
        xs[nl * (IN + 1) + i] = (n < NN) ? X[(size_t)n * IN + i] : 0.f;
    }
    int nq = t & 15, cq = t >> 4;
    int c0 = cq * 4;
    for (int cc = 0; cc < 4; cc++) {
        __syncthreads();
        for (int idx = t; idx < IN * 64; idx += 256)
            ws[idx] = W[cc * IN * 64 + idx];
        __syncthreads();
        float acc[4][4];
#pragma unroll
        for (int r = 0; r < 4; r++)
#pragma unroll
            for (int j = 0; j < 4; j++) acc[r][j] = 0.f;
#pragma unroll 8
        for (int i = 0; i < IN; i++) {
            float4 b = *(const float4*)&ws[i * 64 + c0];
#pragma unroll
            for (int r = 0; r < 4; r++) {
                float av = xs[(nq * 4 + r) * (IN + 1) + i];
                acc[r][0] = fmaf(av, b.x, acc[r][0]);
                acc[r][1] = fmaf(av, b.y, acc[r][1]);
                acc[r][2] = fmaf(av, b.z, acc[r][2]);
                acc[r][3] = fmaf(av, b.w, acc[r][3]);
            }
        }
        float4 bb = *(const float4*)&B[cc * 64 + c0];
#pragma unroll
        for (int r = 0; r < 4; r++) {
            int n = n0 + nq * 4 + r;
            if (n < NN) {
                float4 ov = make_float4(acc[r][0] + bb.x, acc[r][1] + bb.y,
                                        acc[r][2] + bb.z, acc[r][3] + bb.w);
                *(float4*)&OUT[(size_t)n * 256 + cc * 64 + c0] = ov;
            }
        }
    }
}

// ---------------- pass A: scores, exp, denominators ------------------------
// block = 256 thr = 8 warps, 32 edges/block. warp w: head = w&1, edge group = w>>1 (8 edges).
__global__ void k_scores(const int* __restrict__ ei,
                         const float* __restrict__ Wex, const float* __restrict__ attx,
                         const float* __restrict__ Weh, const float* __restrict__ atth) {
    __shared__ __align__(16) float se[512];
    __shared__ int ssrc[32], sdst[32];
    int t = threadIdx.x;
    int e0 = blockIdx.x * 32;  // EE divisible by 32
    if (t < 32) { ssrc[t] = ei[e0 + t]; sdst[t] = ei[EE + e0 + t]; }
    ((float2*)se)[t] = ((const float2*)(g_e + (size_t)e0 * 16))[t];
    __syncthreads();

    int w = t >> 5, lane = t & 31;
    int h = w & 1, grp = w >> 1;
    int ch = h * 32 + lane;

#pragma unroll 1
    for (int p = 0; p < 2; p++) {
        const float* __restrict__ XL = p ? g_XLh : g_XLx;
        const float* __restrict__ XR = p ? g_XRh : g_XRx;
        const float* __restrict__ We = p ? Weh : Wex;
        const float* __restrict__ att = p ? atth : attx;
#pragma unroll 1
        for (int g = 0; g < 4; g++) {
            float wcol[16];
#pragma unroll
            for (int k = 0; k < 16; k++) wcol[k] = We[(g * 16 + k) * 64 + ch];
            float av = att[g * 64 + ch];
            int qi = p * 8 + g * 2 + h;
#pragma unroll 2
            for (int j = 0; j < 8; j++) {
                int ej = grp * 8 + j;
                int s = ssrc[ej], d = sdst[ej];
                float ee = 0.f;
#pragma unroll
                for (int k = 0; k < 16; k++) ee = fmaf(se[ej * 16 + k], wcol[k], ee);
                float m = XL[(size_t)s * 256 + g * 64 + ch] +
                          XR[(size_t)d * 256 + g * 64 + ch] + ee;
                float lr = m > 0.f ? m : 0.2f * m;
                float sc = lr * av;
#pragma unroll
                for (int off = 16; off; off >>= 1)
                    sc += __shfl_xor_sync(0xffffffffu, sc, off);
                if (lane == 0) {
                    float ex = __expf(sc);
                    g_EX[(size_t)(e0 + ej) * 16 + qi] = ex;
                    atomicAdd(&g_DEN[(size_t)d * 16 + qi], ex);
                }
            }
        }
    }
}

// ---------------- pass B: alpha-weighted aggregation -----------------------
// warp per edge. lane -> (gate half, 4 channels). Vectorized red.add.v4.f32.
__global__ void k_agg(const int* __restrict__ ei) {
    int w = threadIdx.x >> 5, lane = threadIdx.x & 31;
    int e = blockIdx.x * 8 + w;  // EE divisible by 8
    int s = ei[e], d = ei[EE + e];
    float al = 0.f;
    if (lane < 16) {
        float ex = g_EX[(size_t)e * 16 + lane];
        float dn = g_DEN[(size_t)d * 16 + lane];
        al = ex / dn;
    }
    int hh = (lane >> 3) & 1;      // head of this lane's channel quad
    int ch4 = (lane & 15) * 4;     // channel offset within gate (0..60)
    int ghalf = lane >> 4;         // which gate of the pair
#pragma unroll
    for (int gp = 0; gp < 2; gp++) {
        int g = gp * 2 + ghalf;
        float ax = __shfl_sync(0xffffffffu, al, g * 2 + hh);
        float ah = __shfl_sync(0xffffffffu, al, 8 + g * 2 + hh);
        float4 vx = *(const float4*)&g_XLx[(size_t)s * 256 + g * 64 + ch4];
        float4 vh = *(const float4*)&g_XLh[(size_t)s * 256 + g * 64 + ch4];
        float4 r;
        r.x = fmaf(ax, vx.x, ah * vh.x);
        r.y = fmaf(ax, vx.y, ah * vh.y);
        r.z = fmaf(ax, vx.z, ah * vh.z);
        r.w = fmaf(ax, vx.w, ah * vh.w);
        float* ptr = &g_GATES[(size_t)d * 256 + g * 64 + ch4];
        asm volatile("red.global.add.v4.f32 [%0], {%1,%2,%3,%4};"
                     :: "l"(ptr), "f"(r.x), "f"(r.y), "f"(r.z), "f"(r.w)
                     : "memory");
    }
}

// ---------------- final: LSTM gates + LayerNorm ----------------------------
// warp per node; lane owns channels (lane, lane+32).
__global__ void k_final(const float* __restrict__ c_prev,
                        const float* __restrict__ biasx, const float* __restrict__ biash,
                        const float* __restrict__ gamma, const float* __restrict__ beta,
                        float* __restrict__ out) {
    int w = threadIdx.x >> 5, lane = threadIdx.x & 31;
    int n = blockIdx.x * 8 + w;  // NN divisible by 8
    float res[2], cs[2];
    float sum = 0.f, sq = 0.f;
#pragma unroll
    for (int half = 0; half < 2; half++) {
        int ch = lane + half * 32;
        float a[4];
#pragma unroll
        for (int g = 0; g < 4; g++)
            a[g] = g_GATES[(size_t)n * 256 + g * 64 + ch] +
                   biasx[g * 64 + ch] + biash[g * 64 + ch];
        float it = 1.f / (1.f + __expf(-a[0]));
        float ft = 1.f / (1.f + __expf(-a[1]));
        float ot = 1.f / (1.f + __expf(-a[2]));
        float gt = tanhf(a[3]);
        float cp = c_prev[(size_t)n * 64 + ch];
        float c = ft * cp + it * gt;
        float hp = ot * tanhf(c);
        cs[half] = c;
        res[half] = hp;
        sum += hp;
        sq = fmaf(hp, hp, sq);
    }
#pragma unroll
    for (int off = 16; off; off >>= 1) {
        sum += __shfl_xor_sync(0xffffffffu, sum, off);
        sq += __shfl_xor_sync(0xffffffffu, sq, off);
    }
    float mu = sum * (1.f / 64.f);
    float var = sq * (1.f / 64.f) - mu * mu;
    float inv = rsqrtf(var + 1e-5f);
#pragma unroll
    for (int half = 0; half < 2; half++) {
        int ch = lane + half * 32;
        float hn = (res[half] - mu) * inv * gamma[ch] + beta[ch];
        out[(size_t)n * 64 + ch] = hn;
        out[(size_t)NN * 64 + (size_t)n * 64 + ch] = cs[half];
    }
}

// ---------------- launch ----------------------------------------------------
extern "C" void kernel_launch(void* const* d_in, const int* in_sizes, int n_in,
                              void* d_out, int out_size) {
    const float* x_t    = (const float*)d_in[0];
    const float* h_prev = (const float*)d_in[1];
    const float* c_prev = (const float*)d_in[2];
    const int*   ei     = (const int*)d_in[3];
    const float* ea     = (const float*)d_in[4];
    const float* Wm1    = (const float*)d_in[5];
    const float* bm1    = (const float*)d_in[6];
    const float* Wm2    = (const float*)d_in[7];
    const float* bm2    = (const float*)d_in[8];
    const float* Wlx    = (const float*)d_in[9];
    const float* blx    = (const float*)d_in[10];
    const float* Wrx    = (const float*)d_in[11];
    const float* brx    = (const float*)d_in[12];
    const float* Wex    = (const float*)d_in[13];
    const float* attx   = (const float*)d_in[14];
    const float* biasx  = (const float*)d_in[15];
    const float* Wlh    = (const float*)d_in[16];
    const float* blh    = (const float*)d_in[17];
    const float* Wrh    = (const float*)d_in[18];
    const float* brh    = (const float*)d_in[19];
    const float* Weh    = (const float*)d_in[20];
    const float* atth   = (const float*)d_in[21];
    const float* biash  = (const float*)d_in[22];
    const float* gamma  = (const float*)d_in[23];
    const float* beta   = (const float*)d_in[24];

    float *pXLx, *pXRx, *pXLh, *pXRh;
    cudaGetSymbolAddress((void**)&pXLx, g_XLx);
    cudaGetSymbolAddress((void**)&pXRx, g_XRx);
    cudaGetSymbolAddress((void**)&pXLh, g_XLh);
    cudaGetSymbolAddress((void**)&pXRh, g_XRh);

    k_zero<<<12500, 256>>>();
    k_edge_mlp<<<EE / 256, 256>>>(ea, Wm1, bm1, Wm2, bm2);
    k_proj<32><<<(NN + 63) / 64, 256>>>(x_t, Wlx, blx, pXLx);
    k_proj<32><<<(NN + 63) / 64, 256>>>(x_t, Wrx, brx, pXRx);
    k_proj<64><<<(NN + 63) / 64, 256>>>(h_prev, Wlh, blh, pXLh);
    k_proj<64><<<(NN + 63) / 64, 256>>>(h_prev, Wrh, brh, pXRh);
    k_scores<<<EE / 32, 256>>>(ei, Wex, attx, Weh, atth);
    k_agg<<<EE / 8, 256>>>(ei);
    k_final<<<NN / 8, 256>>>(c_prev, biasx, biash, gamma, beta, (float*)d_out);
}

// round 2
// speedup vs baseline: 1.2838x; 1.2838x over previous
#include <cuda_runtime.h>
#include <math.h>
#include <stdint.h>

#define NN 50000
#define EE 800000

typedef unsigned long long ull;

// ---------------- scratch (device globals) ----------------------------------
__device__ float g_e[(size_t)EE * 16];                   // edge MLP output
__device__ __align__(16) float g_L[(size_t)NN * 512];    // [n][p*256+g*64+c]  lin_l proj
__device__ __align__(16) float g_R[(size_t)NN * 512];    // lin_r proj
__device__ __align__(16) float g_NUM[(size_t)NN * 512];  // unnormalized agg numerators
__device__ float g_DEN[(size_t)NN * 16];                 // softmax denominators [p*8+g*2+h]

// ---------------- f32x2 packed helpers --------------------------------------
__device__ __forceinline__ ull pack2(float a, float b) {
    ull r; asm("mov.b64 %0,{%1,%2};" : "=l"(r) : "f"(a), "f"(b)); return r;
}
__device__ __forceinline__ void unpack2(float& a, float& b, ull v) {
    asm("mov.b64 {%0,%1},%2;" : "=f"(a), "=f"(b) : "l"(v));
}
__device__ __forceinline__ ull fma2(ull a, ull b, ull c) {
    ull d; asm("fma.rn.f32x2 %0,%1,%2,%3;" : "=l"(d) : "l"(a), "l"(b), "l"(c)); return d;
}

// ---------------- zero init --------------------------------------------------
__global__ void k_zero() {
    size_t i = (size_t)blockIdx.x * blockDim.x + threadIdx.x;
    const float4 z = make_float4(0.f, 0.f, 0.f, 0.f);
    if (i < (size_t)NN * 512 / 4) ((float4*)g_NUM)[i] = z;
    if (i < (size_t)NN * 16 / 4) ((float4*)g_DEN)[i] = z;
}

// ---------------- edge MLP: e = gelu(ea@Wm1+bm1)@Wm2+bm2 --------------------
__global__ void k_edge_mlp(const float* __restrict__ ea,
                           const float* __restrict__ Wm1, const float* __restrict__ bm1,
                           const float* __restrict__ Wm2, const float* __restrict__ bm2) {
    __shared__ float sW1[256], sW2[256], sb1[16], sb2[16];
    int t = threadIdx.x;
    sW1[t] = Wm1[t];
    sW2[t] = Wm2[t];
    if (t < 16) { sb1[t] = bm1[t]; sb2[t] = bm2[t]; }
    __syncthreads();
    int e = blockIdx.x * 256 + t;

    float4 va[4];
    const float4* p = (const float4*)(ea + (size_t)e * 16);
    va[0] = p[0]; va[1] = p[1]; va[2] = p[2]; va[3] = p[3];
    const float* a = (const float*)va;

    float h[16];
#pragma unroll
    for (int j = 0; j < 16; j++) {
        float s = sb1[j];
#pragma unroll
        for (int k = 0; k < 16; k++) s = fmaf(a[k], sW1[k * 16 + j], s);
        h[j] = 0.5f * s * (1.0f + erff(s * 0.70710678118654752f));
    }
    float4 vo[4];
    float* o = (float*)vo;
#pragma unroll
    for (int j = 0; j < 16; j++) {
        float s = sb2[j];
#pragma unroll
        for (int k = 0; k < 16; k++) s = fmaf(h[k], sW2[k * 16 + j], s);
        o[j] = s;
    }
    float4* q = (float4*)(g_e + (size_t)e * 16);
    q[0] = vo[0]; q[1] = vo[1]; q[2] = vo[2]; q[3] = vo[3];
}

// ---------------- node projections into combined tables ---------------------
// grid.y: 0 -> (W0,B0) into g_L, 1 -> (W1,B1) into g_R. poff: 0 for x, 256 for h.
template <int IN>
__global__ void k_proj(const float* __restrict__ X,
                       const float* __restrict__ W0, const float* __restrict__ B0,
                       const float* __restrict__ W1, const float* __restrict__ B1,
                       int poff) {
    const float* __restrict__ W = blockIdx.y ? W1 : W0;
    const float* __restrict__ B = blockIdx.y ? B1 : B0;
    float* __restrict__ OUT = blockIdx.y ? g_R : g_L;

    __shared__ __align__(16) float xs[64 * (IN + 1)];
    __shared__ __align__(16) float ws[IN * 64];
    int t = threadIdx.x;
    int n0 = blockIdx.x * 64;
    for (int idx = t; idx < 64 * IN; idx += 256) {
        int nl = idx / IN, i = idx % IN;
        int n = n0 + nl;
        xs[nl * (IN + 1) + i] = (n < NN) ? X[(size_t)n * IN + i] : 0.f;
    }
    int nq = t & 15, cq = t >> 4;
    int c0 = cq * 4;
    for (int cc = 0; cc < 4; cc++) {
        __syncthreads();
        for (int idx = t; idx < IN * 64; idx += 256)
            ws[idx] = W[cc * IN * 64 + idx];
        __syncthreads();
        float acc[4][4];
#pragma unroll
        for (int r = 0; r < 4; r++)
#pragma unroll
            for (int j = 0; j < 4; j++) acc[r][j] = 0.f;
#pragma unroll 8
        for (int i = 0; i < IN; i++) {
            float4 b = *(const float4*)&ws[i * 64 + c0];
#pragma unroll
            for (int r = 0; r < 4; r++) {
                float av = xs[(nq * 4 + r) * (IN + 1) + i];
                acc[r][0] = fmaf(av, b.x, acc[r][0]);
                acc[r][1] = fmaf(av, b.y, acc[r][1]);
                acc[r][2] = fmaf(av, b.z, acc[r][2]);
                acc[r][3] = fmaf(av, b.w, acc[r][3]);
            }
        }
        float4 bb = *(const float4*)&B[cc * 64 + c0];
#pragma unroll
        for (int r = 0; r < 4; r++) {
            int n = n0 + nq * 4 + r;
            if (n < NN) {
                float4 ov = make_float4(acc[r][0] + bb.x, acc[r][1] + bb.y,
                                        acc[r][2] + bb.z, acc[r][3] + bb.w);
                *(float4*)&OUT[(size_t)n * 512 + poff + cc * 64 + c0] = ov;
            }
        }
    }
}

// ---------------- fused edge pass: scores + exp + num/den accumulation ------
// block = 256 = 8 warps, 128 edges/block (16 per warp, 8 per half-warp).
// Half-warp covers one edge's 64 channels as float4 per lane.
__global__ __launch_bounds__(256, 2)
void k_scores(const int* __restrict__ ei,
              const float* __restrict__ Wex, const float* __restrict__ attx,
              const float* __restrict__ Weh, const float* __restrict__ atth) {
    __shared__ ull se2[128 * 16];      // edge features, each float duplicated into f32x2
    __shared__ int ssrc[128], sdst[128];
    int t = threadIdx.x;
    int e0 = blockIdx.x * 128;
    if (t < 128) { ssrc[t] = ei[e0 + t]; sdst[t] = ei[EE + e0 + t]; }
    {
        const float4* src4 = (const float4*)(g_e + (size_t)e0 * 16);
        float4 v1 = src4[t * 2], v2 = src4[t * 2 + 1];
        int b = t * 8;
        se2[b + 0] = pack2(v1.x, v1.x); se2[b + 1] = pack2(v1.y, v1.y);
        se2[b + 2] = pack2(v1.z, v1.z); se2[b + 3] = pack2(v1.w, v1.w);
        se2[b + 4] = pack2(v2.x, v2.x); se2[b + 5] = pack2(v2.y, v2.y);
        se2[b + 6] = pack2(v2.z, v2.z); se2[b + 7] = pack2(v2.w, v2.w);
    }
    __syncthreads();

    int w = t >> 5, lane = t & 31;
    int half = lane >> 4, hl = lane & 15;
    int c4 = hl * 4, head = hl >> 3;

#pragma unroll 1
    for (int p = 0; p < 2; p++) {
        const float* __restrict__ We = p ? Weh : Wex;
        const float* __restrict__ att = p ? atth : attx;
#pragma unroll 1
        for (int g = 0; g < 4; g++) {
            ull wl[16], wh[16];
#pragma unroll
            for (int k = 0; k < 16; k++) {
                float4 wv = *(const float4*)&We[(g * 16 + k) * 64 + c4];
                wl[k] = pack2(wv.x, wv.y);
                wh[k] = pack2(wv.z, wv.w);
            }
            float4 a4 = *(const float4*)&att[g * 64 + c4];
            int qi = p * 8 + g * 2 + head;
            int goff = p * 256 + g * 64 + c4;
#pragma unroll 1
            for (int j = 0; j < 8; j++) {
                int ej = w * 16 + j * 2 + half;
                int s = ssrc[ej], d = sdst[ej];
                ull a01 = 0, a23 = 0;
                const ull* ep = &se2[ej * 16];
#pragma unroll
                for (int k = 0; k < 16; k++) {
                    ull ek = ep[k];
                    a01 = fma2(ek, wl[k], a01);
                    a23 = fma2(ek, wh[k], a23);
                }
                float4 xl = *(const float4*)&g_L[(size_t)s * 512 + goff];
                size_t od = (size_t)d * 512 + goff;
                float4 xr = *(const float4*)&g_R[od];
                float ee0, ee1, ee2, ee3;
                unpack2(ee0, ee1, a01);
                unpack2(ee2, ee3, a23);
                float m0 = xl.x + xr.x + ee0, m1 = xl.y + xr.y + ee1;
                float m2 = xl.z + xr.z + ee2, m3 = xl.w + xr.w + ee3;
                float l0 = fmaxf(m0, 0.2f * m0), l1 = fmaxf(m1, 0.2f * m1);
                float l2 = fmaxf(m2, 0.2f * m2), l3 = fmaxf(m3, 0.2f * m3);
                float sc = fmaf(l0, a4.x, fmaf(l1, a4.y, fmaf(l2, a4.z, l3 * a4.w)));
                sc += __shfl_xor_sync(0xffffffffu, sc, 1);
                sc += __shfl_xor_sync(0xffffffffu, sc, 2);
                sc += __shfl_xor_sync(0xffffffffu, sc, 4);
                float ex = __expf(sc);
                float4 r = make_float4(ex * xl.x, ex * xl.y, ex * xl.z, ex * xl.w);
                float* np = &g_NUM[od];
                asm volatile("red.global.add.v4.f32 [%0], {%1,%2,%3,%4};"
                             :: "l"(np), "f"(r.x), "f"(r.y), "f"(r.z), "f"(r.w)
                             : "memory");
                if ((hl & 7) == 0) {
                    float* dp = &g_DEN[(size_t)d * 16 + qi];
                    asm volatile("red.global.add.f32 [%0], %1;"
                                 :: "l"(dp), "f"(ex) : "memory");
                }
            }
        }
    }
}

// ---------------- final: normalize, LSTM gates, LayerNorm -------------------
__global__ void k_final(const float* __restrict__ c_prev,
                        const float* __restrict__ biasx, const float* __restrict__ biash,
                        const float* __restrict__ gamma, const float* __restrict__ beta,
                        float* __restrict__ out) {
    int w = threadIdx.x >> 5, lane = threadIdx.x & 31;
    int n = blockIdx.x * 8 + w;  // NN divisible by 8
    float res[2], cs[2];
    float sum = 0.f, sq = 0.f;
#pragma unroll
    for (int half = 0; half < 2; half++) {
        int ch = lane + half * 32;
        int hh = ch >> 5;
        float a[4];
#pragma unroll
        for (int g = 0; g < 4; g++) {
            float nx = g_NUM[(size_t)n * 512 + g * 64 + ch];
            float nh = g_NUM[(size_t)n * 512 + 256 + g * 64 + ch];
            float dx = g_DEN[(size_t)n * 16 + g * 2 + hh] + 1e-16f;
            float dh = g_DEN[(size_t)n * 16 + 8 + g * 2 + hh] + 1e-16f;
            a[g] = nx / dx + nh / dh + biasx[g * 64 + ch] + biash[g * 64 + ch];
        }
        float it = 1.f / (1.f + __expf(-a[0]));
        float ft = 1.f / (1.f + __expf(-a[1]));
        float ot = 1.f / (1.f + __expf(-a[2]));
        float gt = tanhf(a[3]);
        float cp = c_prev[(size_t)n * 64 + ch];
        float c = ft * cp + it * gt;
        float hp = ot * tanhf(c);
        cs[half] = c;
        res[half] = hp;
        sum += hp;
        sq = fmaf(hp, hp, sq);
    }
#pragma unroll
    for (int off = 16; off; off >>= 1) {
        sum += __shfl_xor_sync(0xffffffffu, sum, off);
        sq += __shfl_xor_sync(0xffffffffu, sq, off);
    }
    float mu = sum * (1.f / 64.f);
    float var = sq * (1.f / 64.f) - mu * mu;
    float inv = rsqrtf(var + 1e-5f);
#pragma unroll
    for (int half = 0; half < 2; half++) {
        int ch = lane + half * 32;
        float hn = (res[half] - mu) * inv * gamma[ch] + beta[ch];
        out[(size_t)n * 64 + ch] = hn;
        out[(size_t)NN * 64 + (size_t)n * 64 + ch] = cs[half];
    }
}

// ---------------- launch -----------------------------------------------------
extern "C" void kernel_launch(void* const* d_in, const int* in_sizes, int n_in,
                              void* d_out, int out_size) {
    const float* x_t    = (const float*)d_in[0];
    const float* h_prev = (const float*)d_in[1];
    const float* c_prev = (const float*)d_in[2];
    const int*   ei     = (const int*)d_in[3];
    const float* ea     = (const float*)d_in[4];
    const float* Wm1    = (const float*)d_in[5];
    const float* bm1    = (const float*)d_in[6];
    const float* Wm2    = (const float*)d_in[7];
    const float* bm2    = (const float*)d_in[8];
    const float* Wlx    = (const float*)d_in[9];
    const float* blx    = (const float*)d_in[10];
    const float* Wrx    = (const float*)d_in[11];
    const float* brx    = (const float*)d_in[12];
    const float* Wex    = (const float*)d_in[13];
    const float* attx   = (const float*)d_in[14];
    const float* biasx  = (const float*)d_in[15];
    const float* Wlh    = (const float*)d_in[16];
    const float* blh    = (const float*)d_in[17];
    const float* Wrh    = (const float*)d_in[18];
    const float* brh    = (const float*)d_in[19];
    const float* Weh    = (const float*)d_in[20];
    const float* atth   = (const float*)d_in[21];
    const float* biash  = (const float*)d_in[22];
    const float* gamma  = (const float*)d_in[23];
    const float* beta   = (const float*)d_in[24];

    k_zero<<<25000, 256>>>();
    k_edge_mlp<<<EE / 256, 256>>>(ea, Wm1, bm1, Wm2, bm2);
    dim3 gp((NN + 63) / 64, 2);
    k_proj<32><<<gp, 256>>>(x_t, Wlx, blx, Wrx, brx, 0);
    k_proj<64><<<gp, 256>>>(h_prev, Wlh, blh, Wrh, brh, 256);
    k_scores<<<EE / 128, 256>>>(ei, Wex, attx, Weh, atth);
    k_final<<<NN / 8, 256>>>(c_prev, biasx, biash, gamma, beta, (float*)d_out);
}

// round 3
// speedup vs baseline: 1.3235x; 1.0309x over previous
#include <cuda_runtime.h>
#include <math.h>
#include <stdint.h>

#define NN 50000
#define EE 800000

typedef unsigned long long ull;

// ---------------- scratch (device globals) ----------------------------------
__device__ int g_cnt[NN];          // per-dst degree (histogram)
__device__ int g_rowptr[NN];       // exclusive prefix sum of cnt
__device__ int g_rowfill[NN];      // scatter fill cursors
__device__ int g_aux[128], g_auxs[128];
__device__ int g_src_sorted[EE];   // src node of dst-sorted edge
__device__ int g_eid_sorted[EE];   // original edge id of dst-sorted edge
__device__ __align__(16) ull   g_e2[(size_t)EE * 16];   // edge feats, dup-packed f32x2, sorted order
__device__ __align__(16) float g_L[(size_t)NN * 512];   // [n][p*256+g*64+c]  lin_l proj
__device__ __align__(16) float g_R[(size_t)NN * 512];   // lin_r proj
__device__ __align__(16) float g_NUM[(size_t)NN * 512]; // unnormalized agg numerators
__device__ float g_DEN[(size_t)NN * 16];                // softmax denominators [p*8+g*2+h]

// ---------------- f32x2 packed helpers --------------------------------------
__device__ __forceinline__ ull pack2(float a, float b) {
    ull r; asm("mov.b64 %0,{%1,%2};" : "=l"(r) : "f"(a), "f"(b)); return r;
}
__device__ __forceinline__ void unpack2(float& a, float& b, ull v) {
    asm("mov.b64 {%0,%1},%2;" : "=f"(a), "=f"(b) : "l"(v));
}
__device__ __forceinline__ ull fma2(ull a, ull b, ull c) {
    ull d; asm("fma.rn.f32x2 %0,%1,%2,%3;" : "=l"(d) : "l"(a), "l"(b), "l"(c)); return d;
}
__device__ __forceinline__ ull add2(ull a, ull b) {
    ull d; asm("add.rn.f32x2 %0,%1,%2;" : "=l"(d) : "l"(a), "l"(b)); return d;
}

// ---------------- counting sort by dst ---------------------------------------
__global__ void k_init() {
    int i = blockIdx.x * 256 + threadIdx.x;
    if (i < NN) g_cnt[i] = 0;
}
__global__ void k_hist(const int* __restrict__ ei) {
    int e = blockIdx.x * 256 + threadIdx.x;
    atomicAdd(&g_cnt[ei[EE + e]], 1);
}
__global__ void k_scan_a() {
    __shared__ int s[512];
    int t = threadIdx.x;
    int i = blockIdx.x * 512 + t;
    int v = (i < NN) ? g_cnt[i] : 0;
    s[t] = v;
    __syncthreads();
#pragma unroll
    for (int off = 1; off < 512; off <<= 1) {
        int u = (t >= off) ? s[t - off] : 0;
        __syncthreads();
        s[t] += u;
        __syncthreads();
    }
    if (i < NN) g_rowptr[i] = s[t] - v;
    if (t == 511) g_aux[blockIdx.x] = s[511];
}
__global__ void k_scan_b() {
    if (threadIdx.x == 0) {
        int r = 0;
        for (int i = 0; i < 98; i++) { int t = g_aux[i]; g_auxs[i] = r; r += t; }
    }
}
__global__ void k_scan_c() {
    int i = blockIdx.x * 512 + threadIdx.x;
    if (i < NN) {
        int v = g_rowptr[i] + g_auxs[blockIdx.x];
        g_rowptr[i] = v;
        g_rowfill[i] = v;
    }
}
__global__ void k_scatter(const int* __restrict__ ei) {
    int e = blockIdx.x * 256 + threadIdx.x;
    int d = ei[EE + e];
    int pos = atomicAdd(&g_rowfill[d], 1);
    g_src_sorted[pos] = ei[e];
    g_eid_sorted[pos] = e;
}

// ---------------- edge MLP (into sorted slots, dup-packed) -------------------
__global__ void k_edge_mlp(const float* __restrict__ ea,
                           const float* __restrict__ Wm1, const float* __restrict__ bm1,
                           const float* __restrict__ Wm2, const float* __restrict__ bm2) {
    __shared__ float sW1[256], sW2[256], sb1[16], sb2[16];
    int t = threadIdx.x;
    sW1[t] = Wm1[t];
    sW2[t] = Wm2[t];
    if (t < 16) { sb1[t] = bm1[t]; sb2[t] = bm2[t]; }
    __syncthreads();
    int i = blockIdx.x * 256 + t;
    int eid = g_eid_sorted[i];

    float4 va[4];
    const float4* p = (const float4*)(ea + (size_t)eid * 16);
    va[0] = p[0]; va[1] = p[1]; va[2] = p[2]; va[3] = p[3];
    const float* a = (const float*)va;

    float h[16];
#pragma unroll
    for (int j = 0; j < 16; j++) {
        float s = sb1[j];
#pragma unroll
        for (int k = 0; k < 16; k++) s = fmaf(a[k], sW1[k * 16 + j], s);
        h[j] = 0.5f * s * (1.0f + erff(s * 0.70710678118654752f));
    }
    ull* q = g_e2 + (size_t)i * 16;
#pragma unroll
    for (int j = 0; j < 16; j++) {
        float s = sb2[j];
#pragma unroll
        for (int k = 0; k < 16; k++) s = fmaf(h[k], sW2[k * 16 + j], s);
        q[j] = pack2(s, s);
    }
}

// ---------------- node projections (z-split over gate chunks) ---------------
template <int IN>
__global__ void k_proj(const float* __restrict__ X,
                       const float* __restrict__ W0, const float* __restrict__ B0,
                       const float* __restrict__ W1, const float* __restrict__ B1,
                       int poff) {
    const float* __restrict__ W = blockIdx.y ? W1 : W0;
    const float* __restrict__ B = blockIdx.y ? B1 : B0;
    float* __restrict__ OUT = blockIdx.y ? g_R : g_L;
    int cc = blockIdx.z;

    __shared__ __align__(16) float xs[64 * (IN + 1)];
    __shared__ __align__(16) float ws[IN * 64];
    int t = threadIdx.x;
    int n0 = blockIdx.x * 64;
    for (int idx = t; idx < 64 * IN; idx += 256) {
        int nl = idx / IN, i = idx % IN;
        int n = n0 + nl;
        xs[nl * (IN + 1) + i] = (n < NN) ? X[(size_t)n * IN + i] : 0.f;
    }
    for (int idx = t; idx < IN * 64; idx += 256)
        ws[idx] = W[cc * IN * 64 + idx];
    __syncthreads();

    int nq = t & 15, cq = t >> 4;
    int c0 = cq * 4;
    float acc[4][4];
#pragma unroll
    for (int r = 0; r < 4; r++)
#pragma unroll
        for (int j = 0; j < 4; j++) acc[r][j] = 0.f;
#pragma unroll 8
    for (int i = 0; i < IN; i++) {
        float4 b = *(const float4*)&ws[i * 64 + c0];
#pragma unroll
        for (int r = 0; r < 4; r++) {
            float av = xs[(nq * 4 + r) * (IN + 1) + i];
            acc[r][0] = fmaf(av, b.x, acc[r][0]);
            acc[r][1] = fmaf(av, b.y, acc[r][1]);
            acc[r][2] = fmaf(av, b.z, acc[r][2]);
            acc[r][3] = fmaf(av, b.w, acc[r][3]);
        }
    }
    float4 bb = *(const float4*)&B[cc * 64 + c0];
#pragma unroll
    for (int r = 0; r < 4; r++) {
        int n = n0 + nq * 4 + r;
        if (n < NN) {
            float4 ov = make_float4(acc[r][0] + bb.x, acc[r][1] + bb.y,
                                    acc[r][2] + bb.z, acc[r][3] + bb.w);
            *(float4*)&OUT[(size_t)n * 512 + poff + cc * 64 + c0] = ov;
        }
    }
}

// ---------------- fused GAT pass: warp per dst node --------------------------
// lane owns 16 consecutive channels [lane*16, lane*16+16) of the 512-channel
// concatenated (pass, gate, channel) space. Softmax segment = lane>>1.
__global__ __launch_bounds__(256)
void k_gat(const float* __restrict__ Wex, const float* __restrict__ attx,
           const float* __restrict__ Weh, const float* __restrict__ atth) {
    __shared__ ull sW[16 * 256];   // [(k*8+jp)*32 + lane] : channel pair (lane*16+jp*2, +1)
    __shared__ float satt[512];
    int t = threadIdx.x;

    for (int idx = t; idx < 4096; idx += 256) {
        int k = idx >> 8, jp = (idx >> 5) & 7, ln = idx & 31;
        int cc0 = ln * 16 + jp * 2;
        int p = cc0 >> 8, g = (cc0 >> 6) & 3, c = cc0 & 63;
        const float* We = p ? Weh : Wex;
        sW[idx] = pack2(We[(g * 16 + k) * 64 + c], We[(g * 16 + k) * 64 + c + 1]);
    }
    for (int idx = t; idx < 512; idx += 256) {
        int p = idx >> 8;
        satt[idx] = (p ? atth : attx)[idx & 255];
    }
    __syncthreads();

    int w = t >> 5, lane = t & 31;
    int n = blockIdx.x * 8 + w;

    float fatt[16];
#pragma unroll
    for (int j = 0; j < 16; j++) fatt[j] = satt[lane * 16 + j];

    ull xr2[8];
    {
        const ull* rp = (const ull*)(g_R + (size_t)n * 512 + lane * 16);
#pragma unroll
        for (int j = 0; j < 8; j++) xr2[j] = rp[j];
    }
    ull num2[8];
#pragma unroll
    for (int j = 0; j < 8; j++) num2[j] = 0;
    float den = 0.f;

    int start = g_rowptr[n], deg = g_cnt[n];
    for (int i = start; i < start + deg; i++) {
        int s = g_src_sorted[i];
        ull xl2[8];
        const ull* lp = (const ull*)(g_L + (size_t)s * 512 + lane * 16);
#pragma unroll
        for (int j = 0; j < 8; j++) xl2[j] = lp[j];

        ull acc[8];
#pragma unroll
        for (int jp = 0; jp < 8; jp++) acc[jp] = add2(xl2[jp], xr2[jp]);

        const ull* ep = g_e2 + (size_t)i * 16;
#pragma unroll
        for (int k = 0; k < 16; k++) {
            ull ek = __ldg(ep + k);
#pragma unroll
            for (int jp = 0; jp < 8; jp++)
                acc[jp] = fma2(ek, sW[(k * 8 + jp) * 32 + lane], acc[jp]);
        }

        float partial = 0.f;
#pragma unroll
        for (int jp = 0; jp < 8; jp++) {
            float m0, m1;
            unpack2(m0, m1, acc[jp]);
            float l0 = fmaxf(m0, 0.2f * m0);
            float l1 = fmaxf(m1, 0.2f * m1);
            partial = fmaf(l0, fatt[jp * 2], fmaf(l1, fatt[jp * 2 + 1], partial));
        }
        float sc = partial + __shfl_xor_sync(0xffffffffu, partial, 1);
        float ex = __expf(sc);
        den += ex;
        ull exx = pack2(ex, ex);
#pragma unroll
        for (int jp = 0; jp < 8; jp++) num2[jp] = fma2(exx, xl2[jp], num2[jp]);
    }

    ull* np = (ull*)(g_NUM + (size_t)n * 512 + lane * 16);
#pragma unroll
    for (int j = 0; j < 8; j++) np[j] = num2[j];
    if ((lane & 1) == 0) g_DEN[(size_t)n * 16 + (lane >> 1)] = den;
}

// ---------------- final: normalize, LSTM gates, LayerNorm -------------------
__global__ void k_final(const float* __restrict__ c_prev,
                        const float* __restrict__ biasx, const float* __restrict__ biash,
                        const float* __restrict__ gamma, const float* __restrict__ beta,
                        float* __restrict__ out) {
    int w = threadIdx.x >> 5, lane = threadIdx.x & 31;
    int n = blockIdx.x * 8 + w;
    float res[2], cs[2];
    float sum = 0.f, sq = 0.f;
#pragma unroll
    for (int half = 0; half < 2; half++) {
        int ch = lane + half * 32;
        int hh = ch >> 5;
        float a[4];
#pragma unroll
        for (int g = 0; g < 4; g++) {
            float nx = g_NUM[(size_t)n * 512 + g * 64 + ch];
            float nh = g_NUM[(size_t)n * 512 + 256 + g * 64 + ch];
            float dx = g_DEN[(size_t)n * 16 + g * 2 + hh] + 1e-16f;
            float dh = g_DEN[(size_t)n * 16 + 8 + g * 2 + hh] + 1e-16f;
            a[g] = nx / dx + nh / dh + biasx[g * 64 + ch] + biash[g * 64 + ch];
        }
        float it = 1.f / (1.f + __expf(-a[0]));
        float ft = 1.f / (1.f + __expf(-a[1]));
        float ot = 1.f / (1.f + __expf(-a[2]));
        float gt = tanhf(a[3]);
        float cp = c_prev[(size_t)n * 64 + ch];
        float c = ft * cp + it * gt;
        float hp = ot * tanhf(c);
        cs[half] = c;
        res[half] = hp;
        sum += hp;
        sq = fmaf(hp, hp, sq);
    }
#pragma unroll
    for (int off = 16; off; off >>= 1) {
        sum += __shfl_xor_sync(0xffffffffu, sum, off);
        sq += __shfl_xor_sync(0xffffffffu, sq, off);
    }
    float mu = sum * (1.f / 64.f);
    float var = sq * (1.f / 64.f) - mu * mu;
    float inv = rsqrtf(var + 1e-5f);
#pragma unroll
    for (int half = 0; half < 2; half++) {
        int ch = lane + half * 32;
        float hn = (res[half] - mu) * inv * gamma[ch] + beta[ch];
        out[(size_t)n * 64 + ch] = hn;
        out[(size_t)NN * 64 + (size_t)n * 64 + ch] = cs[half];
    }
}

// ---------------- launch ------------------------------------------------------
extern "C" void kernel_launch(void* const* d_in, const int* in_sizes, int n_in,
                              void* d_out, int out_size) {
    const float* x_t    = (const float*)d_in[0];
    const float* h_prev = (const float*)d_in[1];
    const float* c_prev = (const float*)d_in[2];
    const int*   ei     = (const int*)d_in[3];
    const float* ea     = (const float*)d_in[4];
    const float* Wm1    = (const float*)d_in[5];
    const float* bm1    = (const float*)d_in[6];
    const float* Wm2    = (const float*)d_in[7];
    const float* bm2    = (const float*)d_in[8];
    const float* Wlx    = (const float*)d_in[9];
    const float* blx    = (const float*)d_in[10];
    const float* Wrx    = (const float*)d_in[11];
    const float* brx    = (const float*)d_in[12];
    const float* Wex    = (const float*)d_in[13];
    const float* attx   = (const float*)d_in[14];
    const float* biasx  = (const float*)d_in[15];
    const float* Wlh    = (const float*)d_in[16];
    const float* blh    = (const float*)d_in[17];
    const float* Wrh    = (const float*)d_in[18];
    const float* brh    = (const float*)d_in[19];
    const float* Weh    = (const float*)d_in[20];
    const float* atth   = (const float*)d_in[21];
    const float* biash  = (const float*)d_in[22];
    const float* gamma  = (const float*)d_in[23];
    const float* beta   = (const float*)d_in[24];

    k_init<<<196, 256>>>();
    k_hist<<<EE / 256, 256>>>(ei);
    k_scan_a<<<98, 512>>>();
    k_scan_b<<<1, 32>>>();
    k_scan_c<<<98, 512>>>();
    k_scatter<<<EE / 256, 256>>>(ei);
    k_edge_mlp<<<EE / 256, 256>>>(ea, Wm1, bm1, Wm2, bm2);
    dim3 gp((NN + 63) / 64, 2, 4);
    k_proj<32><<<gp, 256>>>(x_t, Wlx, blx, Wrx, brx, 0);
    k_proj<64><<<gp, 256>>>(h_prev, Wlh, blh, Wrh, brh, 256);
    k_gat<<<NN / 8, 256>>>(Wex, attx, Weh, atth);
    k_final<<<NN / 8, 256>>>(c_prev, biasx, biash, gamma, beta, (float*)d_out);
}

// round 4
// speedup vs baseline: 1.8313x; 1.3837x over previous
#include <cuda_runtime.h>
#include <math.h>
#include <stdint.h>

#define NN 50000
#define EE 800000
#define NPB 8   // nodes per k_gat block

typedef unsigned long long ull;

// ---------------- scratch (device globals) ----------------------------------
__device__ int g_cnt[NN];          // per-dst degree (histogram)
__device__ int g_rowptr[NN];       // exclusive prefix sum of cnt
__device__ int g_rowfill[NN];      // scatter fill cursors
__device__ int g_aux[128], g_auxs[128];
__device__ int g_src_sorted[EE];   // src node of dst-sorted edge
__device__ int g_eid_sorted[EE];   // original edge id of dst-sorted edge
__device__ __align__(16) ull   g_e2[(size_t)EE * 16];   // edge feats, dup-packed f32x2, sorted order
__device__ __align__(16) float g_L[(size_t)NN * 512];   // [n][p*256+g*64+c]  lin_l proj
__device__ __align__(16) float g_R[(size_t)NN * 512];   // lin_r proj
__device__ __align__(16) float g_NUM[(size_t)NN * 512]; // unnormalized agg numerators
__device__ float g_DEN[(size_t)NN * 16];                // softmax denominators [p*8+g*2+h]

// ---------------- f32x2 packed helpers --------------------------------------
__device__ __forceinline__ ull pack2(float a, float b) {
    ull r; asm("mov.b64 %0,{%1,%2};" : "=l"(r) : "f"(a), "f"(b)); return r;
}
__device__ __forceinline__ void unpack2(float& a, float& b, ull v) {
    asm("mov.b64 {%0,%1},%2;" : "=f"(a), "=f"(b) : "l"(v));
}
__device__ __forceinline__ ull fma2(ull a, ull b, ull c) {
    ull d; asm("fma.rn.f32x2 %0,%1,%2,%3;" : "=l"(d) : "l"(a), "l"(b), "l"(c)); return d;
}
__device__ __forceinline__ ull add2(ull a, ull b) {
    ull d; asm("add.rn.f32x2 %0,%1,%2;" : "=l"(d) : "l"(a), "l"(b)); return d;
}

// ---------------- counting sort by dst ---------------------------------------
__global__ void k_init() {
    int i = blockIdx.x * 256 + threadIdx.x;
    if (i < NN) g_cnt[i] = 0;
}
__global__ void k_hist(const int* __restrict__ ei) {
    int e = blockIdx.x * 256 + threadIdx.x;
    atomicAdd(&g_cnt[ei[EE + e]], 1);
}
__global__ void k_scan_a() {
    __shared__ int s[512];
    int t = threadIdx.x;
    int i = blockIdx.x * 512 + t;
    int v = (i < NN) ? g_cnt[i] : 0;
    s[t] = v;
    __syncthreads();
#pragma unroll
    for (int off = 1; off < 512; off <<= 1) {
        int u = (t >= off) ? s[t - off] : 0;
        __syncthreads();
        s[t] += u;
        __syncthreads();
    }
    if (i < NN) g_rowptr[i] = s[t] - v;
    if (t == 511) g_aux[blockIdx.x] = s[511];
}
__global__ void k_scan_b() {
    if (threadIdx.x == 0) {
        int r = 0;
        for (int i = 0; i < 98; i++) { int t = g_aux[i]; g_auxs[i] = r; r += t; }
    }
}
__global__ void k_scan_c() {
    int i = blockIdx.x * 512 + threadIdx.x;
    if (i < NN) {
        int v = g_rowptr[i] + g_auxs[blockIdx.x];
        g_rowptr[i] = v;
        g_rowfill[i] = v;
    }
}
__global__ void k_scatter(const int* __restrict__ ei) {
    int e = blockIdx.x * 256 + threadIdx.x;
    int d = ei[EE + e];
    int pos = atomicAdd(&g_rowfill[d], 1);
    g_src_sorted[pos] = ei[e];
    g_eid_sorted[pos] = e;
}

// ---------------- edge MLP (into sorted slots, dup-packed) -------------------
__global__ void k_edge_mlp(const float* __restrict__ ea,
                           const float* __restrict__ Wm1, const float* __restrict__ bm1,
                           const float* __restrict__ Wm2, const float* __restrict__ bm2) {
    __shared__ float sW1[256], sW2[256], sb1[16], sb2[16];
    int t = threadIdx.x;
    sW1[t] = Wm1[t];
    sW2[t] = Wm2[t];
    if (t < 16) { sb1[t] = bm1[t]; sb2[t] = bm2[t]; }
    __syncthreads();
    int i = blockIdx.x * 256 + t;
    int eid = g_eid_sorted[i];

    float4 va[4];
    const float4* p = (const float4*)(ea + (size_t)eid * 16);
    va[0] = p[0]; va[1] = p[1]; va[2] = p[2]; va[3] = p[3];
    const float* a = (const float*)va;

    float h[16];
#pragma unroll
    for (int j = 0; j < 16; j++) {
        float s = sb1[j];
#pragma unroll
        for (int k = 0; k < 16; k++) s = fmaf(a[k], sW1[k * 16 + j], s);
        h[j] = 0.5f * s * (1.0f + erff(s * 0.70710678118654752f));
    }
    ull* q = g_e2 + (size_t)i * 16;
#pragma unroll
    for (int j = 0; j < 16; j++) {
        float s = sb2[j];
#pragma unroll
        for (int k = 0; k < 16; k++) s = fmaf(h[k], sW2[k * 16 + j], s);
        q[j] = pack2(s, s);
    }
}

// ---------------- node projections (z-split over gate chunks) ---------------
template <int IN>
__global__ void k_proj(const float* __restrict__ X,
                       const float* __restrict__ W0, const float* __restrict__ B0,
                       const float* __restrict__ W1, const float* __restrict__ B1,
                       int poff) {
    const float* __restrict__ W = blockIdx.y ? W1 : W0;
    const float* __restrict__ B = blockIdx.y ? B1 : B0;
    float* __restrict__ OUT = blockIdx.y ? g_R : g_L;
    int cc = blockIdx.z;

    __shared__ __align__(16) float xs[64 * (IN + 1)];
    __shared__ __align__(16) float ws[IN * 64];
    int t = threadIdx.x;
    int n0 = blockIdx.x * 64;
    for (int idx = t; idx < 64 * IN; idx += 256) {
        int nl = idx / IN, i = idx % IN;
        int n = n0 + nl;
        xs[nl * (IN + 1) + i] = (n < NN) ? X[(size_t)n * IN + i] : 0.f;
    }
    for (int idx = t; idx < IN * 64; idx += 256)
        ws[idx] = W[cc * IN * 64 + idx];
    __syncthreads();

    int nq = t & 15, cq = t >> 4;
    int c0 = cq * 4;
    float acc[4][4];
#pragma unroll
    for (int r = 0; r < 4; r++)
#pragma unroll
        for (int j = 0; j < 4; j++) acc[r][j] = 0.f;
#pragma unroll 8
    for (int i = 0; i < IN; i++) {
        float4 b = *(const float4*)&ws[i * 64 + c0];
#pragma unroll
        for (int r = 0; r < 4; r++) {
            float av = xs[(nq * 4 + r) * (IN + 1) + i];
            acc[r][0] = fmaf(av, b.x, acc[r][0]);
            acc[r][1] = fmaf(av, b.y, acc[r][1]);
            acc[r][2] = fmaf(av, b.z, acc[r][2]);
            acc[r][3] = fmaf(av, b.w, acc[r][3]);
        }
    }
    float4 bb = *(const float4*)&B[cc * 64 + c0];
#pragma unroll
    for (int r = 0; r < 4; r++) {
        int n = n0 + nq * 4 + r;
        if (n < NN) {
            float4 ov = make_float4(acc[r][0] + bb.x, acc[r][1] + bb.y,
                                    acc[r][2] + bb.z, acc[r][3] + bb.w);
            *(float4*)&OUT[(size_t)n * 512 + poff + cc * 64 + c0] = ov;
        }
    }
}

// ---------------- fused GAT pass: 4 warps per node, weights in registers ----
// Block = 128 thr = 4 warps; block owns NPB consecutive dst nodes.
// Warp w owns concat channels [w*128, (w+1)*128); lane owns 4: ch0 = w*128+lane*4.
// Per-lane register weights: sw0/sw1[16] (f32x2 pairs). Edge tile staged in smem.
__global__ __launch_bounds__(128)
void k_gat(const float* __restrict__ Wex, const float* __restrict__ attx,
           const float* __restrict__ Weh, const float* __restrict__ atth) {
    __shared__ __align__(16) ull se[32 * 16];   // tile: 32 edges x 16 dup-packed feats
    __shared__ int ssrc[32];
    int t = threadIdx.x, w = t >> 5, lane = t & 31;
    int ch0 = w * 128 + lane * 4;
    int p = ch0 >> 8, g = (ch0 >> 6) & 3, c = ch0 & 63;
    const float* __restrict__ We = p ? Weh : Wex;
    const float* __restrict__ att = p ? atth : attx;

    ull sw0[16], sw1[16];
#pragma unroll
    for (int k = 0; k < 16; k++) {
        float4 wv = *(const float4*)&We[(g * 16 + k) * 64 + c];
        sw0[k] = pack2(wv.x, wv.y);
        sw1[k] = pack2(wv.z, wv.w);
    }
    float4 a4 = *(const float4*)&att[g * 64 + c];
    int qi = p * 8 + g * 2 + (c >> 5);

    for (int nl = 0; nl < NPB; nl++) {
        int n = blockIdx.x * NPB + nl;
        const ull* rp = (const ull*)(g_R + (size_t)n * 512 + ch0);
        ull xr0 = rp[0], xr1 = rp[1];
        ull num0 = 0, num1 = 0;
        float den = 0.f;
        int start = g_rowptr[n], deg = g_cnt[n];

        for (int base = 0; base < deg; base += 32) {
            int cnt = min(32, deg - base);
            __syncthreads();
            {
                const ull* gsrc = g_e2 + (size_t)(start + base) * 16;
                for (int idx = t; idx < cnt * 16; idx += 128) se[idx] = gsrc[idx];
                if (t < cnt) ssrc[t] = g_src_sorted[start + base + t];
            }
            __syncthreads();
#pragma unroll 2
            for (int j = 0; j < cnt; j++) {
                int s = ssrc[j];
                const ull* lp = (const ull*)(g_L + (size_t)s * 512 + ch0);
                ull xl0 = lp[0], xl1 = lp[1];
                ull acc0 = add2(xl0, xr0), acc1 = add2(xl1, xr1);
                const ull* ep = &se[j * 16];
#pragma unroll
                for (int k = 0; k < 16; k++) {
                    ull ek = ep[k];
                    acc0 = fma2(ek, sw0[k], acc0);
                    acc1 = fma2(ek, sw1[k], acc1);
                }
                float m0, m1, m2, m3;
                unpack2(m0, m1, acc0);
                unpack2(m2, m3, acc1);
                float l0 = fmaxf(m0, 0.2f * m0), l1 = fmaxf(m1, 0.2f * m1);
                float l2 = fmaxf(m2, 0.2f * m2), l3 = fmaxf(m3, 0.2f * m3);
                float sc = fmaf(l0, a4.x, fmaf(l1, a4.y, fmaf(l2, a4.z, l3 * a4.w)));
                sc += __shfl_xor_sync(0xffffffffu, sc, 1);
                sc += __shfl_xor_sync(0xffffffffu, sc, 2);
                sc += __shfl_xor_sync(0xffffffffu, sc, 4);
                float ex = __expf(sc);
                den += ex;
                ull exx = pack2(ex, ex);
                num0 = fma2(exx, xl0, num0);
                num1 = fma2(exx, xl1, num1);
            }
        }
        ull* np = (ull*)(g_NUM + (size_t)n * 512 + ch0);
        np[0] = num0;
        np[1] = num1;
        if ((lane & 7) == 0) g_DEN[(size_t)n * 16 + qi] = den;
    }
}

// ---------------- final: normalize, LSTM gates, LayerNorm -------------------
__global__ void k_final(const float* __restrict__ c_prev,
                        const float* __restrict__ biasx, const float* __restrict__ biash,
                        const float* __restrict__ gamma, const float* __restrict__ beta,
                        float* __restrict__ out) {
    int w = threadIdx.x >> 5, lane = threadIdx.x & 31;
    int n = blockIdx.x * 8 + w;
    float res[2], cs[2];
    float sum = 0.f, sq = 0.f;
#pragma unroll
    for (int half = 0; half < 2; half++) {
        int ch = lane + half * 32;
        int hh = ch >> 5;
        float a[4];
#pragma unroll
        for (int g = 0; g < 4; g++) {
            float nx = g_NUM[(size_t)n * 512 + g * 64 + ch];
            float nh = g_NUM[(size_t)n * 512 + 256 + g * 64 + ch];
            float dx = g_DEN[(size_t)n * 16 + g * 2 + hh] + 1e-16f;
            float dh = g_DEN[(size_t)n * 16 + 8 + g * 2 + hh] + 1e-16f;
            a[g] = nx / dx + nh / dh + biasx[g * 64 + ch] + biash[g * 64 + ch];
        }
        float it = 1.f / (1.f + __expf(-a[0]));
        float ft = 1.f / (1.f + __expf(-a[1]));
        float ot = 1.f / (1.f + __expf(-a[2]));
        float gt = tanhf(a[3]);
        float cp = c_prev[(size_t)n * 64 + ch];
        float c = ft * cp + it * gt;
        float hp = ot * tanhf(c);
        cs[half] = c;
        res[half] = hp;
        sum += hp;
        sq = fmaf(hp, hp, sq);
    }
#pragma unroll
    for (int off = 16; off; off >>= 1) {
        sum += __shfl_xor_sync(0xffffffffu, sum, off);
        sq += __shfl_xor_sync(0xffffffffu, sq, off);
    }
    float mu = sum * (1.f / 64.f);
    float var = sq * (1.f / 64.f) - mu * mu;
    float inv = rsqrtf(var + 1e-5f);
#pragma unroll
    for (int half = 0; half < 2; half++) {
        int ch = lane + half * 32;
        float hn = (res[half] - mu) * inv * gamma[ch] + beta[ch];
        out[(size_t)n * 64 + ch] = hn;
        out[(size_t)NN * 64 + (size_t)n * 64 + ch] = cs[half];
    }
}

// ---------------- launch ------------------------------------------------------
extern "C" void kernel_launch(void* const* d_in, const int* in_sizes, int n_in,
                              void* d_out, int out_size) {
    const float* x_t    = (const float*)d_in[0];
    const float* h_prev = (const float*)d_in[1];
    const float* c_prev = (const float*)d_in[2];
    const int*   ei     = (const int*)d_in[3];
    const float* ea     = (const float*)d_in[4];
    const float* Wm1    = (const float*)d_in[5];
    const float* bm1    = (const float*)d_in[6];
    const float* Wm2    = (const float*)d_in[7];
    const float* bm2    = (const float*)d_in[8];
    const float* Wlx    = (const float*)d_in[9];
    const float* blx    = (const float*)d_in[10];
    const float* Wrx    = (const float*)d_in[11];
    const float* brx    = (const float*)d_in[12];
    const float* Wex    = (const float*)d_in[13];
    const float* attx   = (const float*)d_in[14];
    const float* biasx  = (const float*)d_in[15];
    const float* Wlh    = (const float*)d_in[16];
    const float* blh    = (const float*)d_in[17];
    const float* Wrh    = (const float*)d_in[18];
    const float* brh    = (const float*)d_in[19];
    const float* Weh    = (const float*)d_in[20];
    const float* atth   = (const float*)d_in[21];
    const float* biash  = (const float*)d_in[22];
    const float* gamma  = (const float*)d_in[23];
    const float* beta   = (const float*)d_in[24];

    k_init<<<196, 256>>>();
    k_hist<<<EE / 256, 256>>>(ei);
    k_scan_a<<<98, 512>>>();
    k_scan_b<<<1, 32>>>();
    k_scan_c<<<98, 512>>>();
    k_scatter<<<EE / 256, 256>>>(ei);
    k_edge_mlp<<<EE / 256, 256>>>(ea, Wm1, bm1, Wm2, bm2);
    dim3 gp((NN + 63) / 64, 2, 4);
    k_proj<32><<<gp, 256>>>(x_t, Wlx, blx, Wrx, brx, 0);
    k_proj<64><<<gp, 256>>>(h_prev, Wlh, blh, Wrh, brh, 256);
    k_gat<<<NN / NPB, 128>>>(Wex, attx, Weh, atth);
    k_final<<<NN / 8, 256>>>(c_prev, biasx, biash, gamma, beta, (float*)d_out);
}